// round 17
// baseline (speedup 1.0000x reference)
#include <cuda_runtime.h>
#include <math.h>

typedef unsigned long long ull;

#define BB 64
#define NN 4096
#define DD 128
#define SS 7
#define HH 128
#define MM 256
#define TROWS 128
#define LN_EPS 1e-5f
#define EPSF 1e-8f
#define SCALE 0.08838834764831845f   // 128^-0.5

// ---------------- device scratch ----------------
__device__ __align__(16) float g_slots[BB*SS*HH];
__device__ __align__(16) float g_u[BB*SS*DD];     // folded: SCALE*g*qk - e/128
__device__ float g_c[BB*SS];
__device__ __align__(16) float g_acc[BB*SS*DD];   // sum_n as*x
__device__ float g_sumWM[BB*SS];                  // sum_n as*m
__device__ float g_W[BB*SS];                      // sum_n ws

// transposed weights: T4[k4*J + j] = {W[j][4k4+0..3]} for col-contracted mats.
// WkT4 is the EXCEPTION: row-contracted -> WkT4[h4*128 + d] = {Wk[4h4+0..3][d]}
__device__ __align__(16) float4 WvT4 [32*128];
__device__ __align__(16) float4 WihT4[32*384];
__device__ __align__(16) float4 WhhT4[32*384];
__device__ __align__(16) float4 w1T4 [32*256];
__device__ __align__(16) float4 w2T4 [64*128];
__device__ __align__(16) float4 WqT4 [32*128];
__device__ __align__(16) float4 WkT4 [32*128];

// ---------------- packed f32x2 helpers ----------------
static __device__ __forceinline__ ull pk2(float lo, float hi) {
    ull r; asm("mov.b64 %0,{%1,%2};" : "=l"(r) : "f"(lo), "f"(hi)); return r;
}
static __device__ __forceinline__ void upk2(float& lo, float& hi, ull v) {
    asm("mov.b64 {%0,%1},%2;" : "=f"(lo), "=f"(hi) : "l"(v));
}
static __device__ __forceinline__ ull ffma2(ull a, ull b, ull c) {
    ull d; asm("fma.rn.f32x2 %0,%1,%2,%3;" : "=l"(d) : "l"(a), "l"(b), "l"(c)); return d;
}
static __device__ __forceinline__ ull fadd2(ull a, ull b) {
    ull d; asm("add.rn.f32x2 %0,%1,%2;" : "=l"(d) : "l"(a), "l"(b)); return d;
}
static __device__ __forceinline__ float hsum2(ull v) {
    float lo, hi; upk2(lo, hi, v); return lo + hi;
}
static __device__ __forceinline__ float dot4(float4 a, float4 b) {
    return a.x*b.x + a.y*b.y + a.z*b.z + a.w*b.w;
}

// GEMV with k-major weights: res[s] = sum_k Xs[s*xstr+k] * Wt-row-k[j]
template<int NS, int J, int K4>
static __device__ __forceinline__ void gemvT(const float4* __restrict__ Wt,
                                             const float* Xs, int xstr,
                                             int j, float* res)
{
    ull a[NS];
    #pragma unroll
    for (int s = 0; s < NS; s++) a[s] = 0ull;
    #pragma unroll 4
    for (int k4 = 0; k4 < K4; k4++) {
        ulonglong2 wv = __ldg((const ulonglong2*)(Wt + k4*J + j));
        #pragma unroll
        for (int s = 0; s < NS; s++) {
            ulonglong2 xv = *(const ulonglong2*)&Xs[s*xstr + k4*4];
            a[s] = ffma2(wv.x, xv.x, ffma2(wv.y, xv.y, a[s]));
        }
    }
    #pragma unroll
    for (int s = 0; s < NS; s++) res[s] = hsum2(a[s]);
}

// ---------------- weight transpose (once) ----------------
__global__ void __launch_bounds__(256) k_tr(
    const float* __restrict__ Wv,  const float* __restrict__ Wih,
    const float* __restrict__ Whh, const float* __restrict__ w1,
    const float* __restrict__ w2,  const float* __restrict__ Wq,
    const float* __restrict__ Wk)
{
    int y = blockIdx.y;
    int idx = blockIdx.x*256 + threadIdx.x;
    const float* src; float4* dst; int J, K4;
    if      (y == 0) { src = Wv;  dst = WvT4;  J = 128; K4 = 32; }
    else if (y == 1) { src = Wih; dst = WihT4; J = 384; K4 = 32; }
    else if (y == 2) { src = Whh; dst = WhhT4; J = 384; K4 = 32; }
    else if (y == 3) { src = w1;  dst = w1T4;  J = 256; K4 = 32; }
    else if (y == 4) { src = w2;  dst = w2T4;  J = 128; K4 = 64; }
    else if (y == 5) { src = Wq;  dst = WqT4;  J = 128; K4 = 32; }
    else             { src = Wk;  dst = WkT4;  J = 128; K4 = 32; }
    int n = J*K4;
    if (idx >= n) return;
    int k4 = idx / J, j = idx - k4*J;
    int K = K4*4;
    if (y == 6) {
        // FIX R16: Wk is row-contracted (qk[d] = sum_h q[h]*Wk[h][d]):
        // store identity copy into k-major layout, NOT the transpose.
        dst[idx] = make_float4(src[(4*k4+0)*J + j], src[(4*k4+1)*J + j],
                               src[(4*k4+2)*J + j], src[(4*k4+3)*J + j]);
    } else {
        dst[idx] = make_float4(src[j*K + 4*k4 + 0], src[j*K + 4*k4 + 1],
                               src[j*K + 4*k4 + 2], src[j*K + 4*k4 + 3]);
    }
}

// ---------------- full prep (device, 7 slots) — used by k_init0 ----------
static __device__ void prep_full(
    int b, int tid,
    const float* slots_sm,
    float* sn, float* q, float* red,
    const float* __restrict__ ln_s_g, const float* __restrict__ ln_s_b,
    const float* __restrict__ ln_in_g, const float* __restrict__ ln_in_b)
{
    int wid = tid >> 5, lane = tid & 31;
    if (tid < 16) red[tid] = 0.f;
    __syncthreads();

    if (tid < 128) {
        for (int s = wid; s < SS; s += 4) {
            float4 x = *(const float4*)&slots_sm[s*HH + lane*4];
            float sm = x.x+x.y+x.z+x.w;
            float sq = dot4(x, x);
            #pragma unroll
            for (int o = 16; o; o >>= 1) {
                sm += __shfl_xor_sync(0xffffffffu, sm, o);
                sq += __shfl_xor_sync(0xffffffffu, sq, o);
            }
            float m   = sm * (1.f/HH);
            float inv = rsqrtf(sq*(1.f/HH) - m*m + LN_EPS);
            int d = lane*4;
            sn[s*HH+d+0] = (x.x-m)*inv*ln_s_g[d+0] + ln_s_b[d+0];
            sn[s*HH+d+1] = (x.y-m)*inv*ln_s_g[d+1] + ln_s_b[d+1];
            sn[s*HH+d+2] = (x.z-m)*inv*ln_s_g[d+2] + ln_s_b[d+2];
            sn[s*HH+d+3] = (x.w-m)*inv*ln_s_g[d+3] + ln_s_b[d+3];
        }
    }
    __syncthreads();

    if (tid < 128) {
        float a7[SS];
        gemvT<SS,128,32>(WqT4, sn, HH, tid, a7);
        #pragma unroll
        for (int s = 0; s < SS; s++) q[s*HH+tid] = a7[s];
    }
    __syncthreads();

    float acc[SS];
    if (tid < 128) {
        int d = tid;
        gemvT<SS,128,32>(WkT4, q, HH, d, acc);
        float gg  = ln_in_g[d];
        float bbv = ln_in_b[d];
        float pe[SS], pc[SS];
        #pragma unroll
        for (int s = 0; s < SS; s++) {
            pe[s] = SCALE * gg  * acc[s];
            pc[s] = SCALE * bbv * acc[s];
        }
        #pragma unroll
        for (int o = 16; o; o >>= 1) {
            #pragma unroll
            for (int s = 0; s < SS; s++) {
                pe[s] += __shfl_xor_sync(0xffffffffu, pe[s], o);
                pc[s] += __shfl_xor_sync(0xffffffffu, pc[s], o);
            }
        }
        if (lane == 0) {
            #pragma unroll
            for (int s = 0; s < SS; s++) {
                atomicAdd(&red[s],   pe[s]);
                atomicAdd(&red[8+s], pc[s]);
            }
        }
    }
    __syncthreads();

    if (tid < 128) {
        int d = tid;
        float gg = ln_in_g[d];
        #pragma unroll
        for (int s = 0; s < SS; s++)
            g_u[(b*SS+s)*DD + d] = SCALE*gg*acc[s] - red[s]*(1.f/DD);
    }
    if (tid < SS) {
        g_c[b*SS+tid]     = red[8+tid];
        g_W[b*SS+tid]     = 0.f;
        g_sumWM[b*SS+tid] = 0.f;
    }
    for (int i = tid; i < SS*DD; i += blockDim.x) g_acc[b*SS*DD + i] = 0.f;
}

// ---------------- init + first prep ----------------
__global__ void __launch_bounds__(128) k_init0(
    const float* __restrict__ sinit,
    const float* __restrict__ mu,
    const float* __restrict__ lsig,
    const float* __restrict__ ln_s_g, const float* __restrict__ ln_s_b,
    const float* __restrict__ ln_in_g, const float* __restrict__ ln_in_b)
{
    __shared__ __align__(16) float T[896*3];
    __shared__ float red[16];
    int b = blockIdx.x, tid = threadIdx.x;
    for (int i = tid; i < SS*HH; i += 128) {
        int s = i >> 7, h = i & 127;
        float v = mu[h] + expf(lsig[h]) * sinit[(b*SS+s)*(HH+4) + h];
        T[i] = v;
        g_slots[b*SS*HH + i] = v;
    }
    __syncthreads();
    prep_full(b, tid, T, T+896, T+1792, red,
              ln_s_g, ln_s_b, ln_in_g, ln_in_b);
}

// ---------------- streaming pass: 128-row tile, all-8-warp pass1 ---------
// gapped layout: row stride 132; float c-offset = c*4 + ((c>>4)<<2)
__global__ void __launch_bounds__(256) k_pass(const float* __restrict__ inputs)
{
    extern __shared__ float smd[];
    float* tile = smd;                              // TROWS*132
    float* ubuf = smd + TROWS*132;                  // 896
    ull*   wbuf = (ull*)(smd + TROWS*132 + 896);    // TROWS*8
    float* sAW  = smd + TROWS*132 + 896 + TROWS*8*2;
    float* sAM  = sAW + 7;

    int b = blockIdx.y, chunk = blockIdx.x;
    int tid = threadIdx.x, wid = tid >> 5, lane = tid & 31;

    if (tid < 224)
        ((float4*)ubuf)[tid] = ((const float4*)(g_u + b*SS*DD))[tid];
    if (tid < 14) { if (tid < 7) sAW[tid] = 0.f; else sAM[tid-7] = 0.f; }

    const float4* gin = (const float4*)(inputs + ((size_t)b*NN + (size_t)chunk*TROWS)*DD);
    #pragma unroll
    for (int j = 0; j < TROWS*32/256; j++) {
        int i = tid + j*256;
        int r = i >> 5, c = i & 31;
        int off = c*4 + ((c >> 4) << 2);
        *(float4*)&tile[r*132 + off] = __ldg(&gin[i]);
    }
    __syncthreads();

    // pass 1: lane-pair per row, all 8 warps. warp w -> rows w*16..w*16+15
    {
        int row  = wid*16 + (lane >> 1);
        int half = lane & 1;
        const float* xr = tile + row*132 + half*68;
        const float* ur = ubuf + half*64;
        float cs[SS];
        #pragma unroll
        for (int s = 0; s < SS; s++) cs[s] = __ldg(&g_c[b*SS+s]);

        ull d2[SS], sm2 = 0ull, sq2 = 0ull;
        #pragma unroll
        for (int s = 0; s < SS; s++) d2[s] = 0ull;
        #pragma unroll 4
        for (int k = 0; k < 16; k++) {
            ulonglong2 x = *(const ulonglong2*)(xr + k*4);
            sm2 = fadd2(sm2, fadd2(x.x, x.y));
            sq2 = ffma2(x.x, x.x, ffma2(x.y, x.y, sq2));
            #pragma unroll
            for (int s = 0; s < SS; s++) {
                ulonglong2 u = *(const ulonglong2*)(ur + s*128 + k*4);
                d2[s] = ffma2(x.x, u.x, ffma2(x.y, u.y, d2[s]));
            }
        }
        float p[SS+2];
        #pragma unroll
        for (int s = 0; s < SS; s++) p[s] = hsum2(d2[s]);
        p[SS]   = hsum2(sm2);
        p[SS+1] = hsum2(sq2);
        #pragma unroll
        for (int j = 0; j < SS+2; j++)
            p[j] += __shfl_xor_sync(0xffffffffu, p[j], 1);

        float m   = p[SS] * (1.f/DD);
        float inv = rsqrtf(p[SS+1]*(1.f/DD) - m*m + LN_EPS);
        float lg[SS], mx = -1e30f;
        #pragma unroll
        for (int s = 0; s < SS; s++) {
            lg[s] = p[s]*inv + cs[s];
            mx = fmaxf(mx, lg[s]);
        }
        float e[SS], sum = 0.f;
        #pragma unroll
        for (int s = 0; s < SS; s++) { e[s] = __expf(lg[s]-mx); sum += e[s]; }
        float isum = __fdividef(1.f, sum);
        float pw[SS], pm[SS];
        #pragma unroll
        for (int s = 0; s < SS; s++) {
            float ws = e[s]*isum + EPSF;
            float as = ws*inv;
            if (half == 0) wbuf[row*8+s] = pk2(as, as);
            pw[s] = ws;
            pm[s] = as*m;
        }
        // warp-sum (each row counted twice -> *0.5)
        #pragma unroll
        for (int o = 16; o; o >>= 1) {
            #pragma unroll
            for (int s = 0; s < SS; s++) {
                pw[s] += __shfl_xor_sync(0xffffffffu, pw[s], o);
                pm[s] += __shfl_xor_sync(0xffffffffu, pm[s], o);
            }
        }
        if (lane == 0) {
            #pragma unroll
            for (int s = 0; s < SS; s++) {
                atomicAdd(&sAW[s], pw[s]*0.5f);
                atomicAdd(&sAM[s], pm[s]*0.5f);
            }
        }
    }
    __syncthreads();

    // pass 2: warp per 16 rows, lanes = d (gapped column offset)
    ull acc[SS][2];
    #pragma unroll
    for (int s = 0; s < SS; s++) { acc[s][0] = 0ull; acc[s][1] = 0ull; }
    {
        int xo = lane*4 + ((lane >> 4) << 2);
        int r0 = wid * 16;
        #pragma unroll 4
        for (int i = 0; i < 16; i++) {
            int r = r0 + i;
            ulonglong2 x = *(const ulonglong2*)&tile[r*132 + xo];
            #pragma unroll
            for (int s = 0; s < SS; s++) {
                ull a = wbuf[r*8 + s];
                acc[s][0] = ffma2(x.x, a, acc[s][0]);
                acc[s][1] = ffma2(x.y, a, acc[s][1]);
            }
        }
    }
    __syncthreads();
    float* red = tile;          // [7][8][128]
    #pragma unroll
    for (int s = 0; s < SS; s++) {
        float4 v;
        upk2(v.x, v.y, acc[s][0]);
        upk2(v.z, v.w, acc[s][1]);
        *(float4*)&red[(s*8+wid)*128 + lane*4] = v;
    }
    __syncthreads();
    if (tid < SS*32) {
        int s = tid >> 5, l = tid & 31;
        float4 t = make_float4(0.f,0.f,0.f,0.f);
        #pragma unroll
        for (int w = 0; w < 8; w++) {
            float4 r = *(const float4*)&red[(s*8+w)*128 + l*4];
            t.x += r.x; t.y += r.y; t.z += r.z; t.w += r.w;
        }
        float* dst = &g_acc[(b*SS+s)*DD + l*4];
        atomicAdd(dst+0, t.x); atomicAdd(dst+1, t.y);
        atomicAdd(dst+2, t.z); atomicAdd(dst+3, t.w);
    }
    if (tid < 2*SS) {
        if (tid < SS) atomicAdd(&g_W[b*SS+tid],        sAW[tid]);
        else          atomicAdd(&g_sumWM[b*SS+tid-SS], sAM[tid-SS]);
    }
}

// ---------------- fused update, slot-split: grid (BB, 2), 4 slots/block --
#define NSL 4
__global__ void __launch_bounds__(512) k_upd(
    const float* __restrict__ ln_in_g, const float* __restrict__ ln_in_b,
    const float* __restrict__ ln_m_g,  const float* __restrict__ ln_m_b,
    const float* __restrict__ ln_s_g,  const float* __restrict__ ln_s_b,
    const float* __restrict__ b_ih, const float* __restrict__ b_hh,
    const float* __restrict__ b1,   const float* __restrict__ b2,
    float* __restrict__ out)
{
    __shared__ __align__(16) float SP [NSL*128];
    __shared__ __align__(16) float Y  [NSL*128];
    __shared__ __align__(16) float UPD[NSL*128];
    __shared__ __align__(16) float GI [NSL*384];
    __shared__ __align__(16) float GH [NSL*384];
    __shared__ __align__(16) float SMD[NSL*128];
    __shared__ __align__(16) float SNM[NSL*128];
    __shared__ __align__(16) float HID[NSL*256];
    __shared__ __align__(16) float SN2[NSL*128];
    __shared__ __align__(16) float Q2 [NSL*128];
    __shared__ float Ws[NSL], SWM[NSL], red[16];

    int b = blockIdx.x, z = blockIdx.y;
    int s0 = z*NSL;
    int tid = threadIdx.x, wid = tid >> 5, lane = tid & 31;

    // ph1: scalars + SP + Y (pad slot -> zeros, W=1)
    if (tid < NSL) {
        bool ex = (s0 + tid) < SS;
        Ws[tid]  = ex ? g_W[b*SS + s0 + tid] : 1.f;
        SWM[tid] = ex ? g_sumWM[b*SS + s0 + tid] : 0.f;
    }
    if (tid < 16) red[tid] = 0.f;
    __syncthreads();
    for (int i = tid; i < NSL*128; i += 512) {
        int sl = i >> 7, d = i & 127;
        bool ex = (s0 + sl) < SS;
        float sp = ex ? g_slots[b*SS*HH + (s0+sl)*128 + d] : 0.f;
        float ac = ex ? g_acc  [b*SS*DD + (s0+sl)*128 + d] : 0.f;
        SP[i] = sp;
        float wv = Ws[sl];
        Y[i] = (ln_in_g[d]*(ac - SWM[sl]) + ln_in_b[d]*wv) * __fdividef(1.f, wv);
    }
    __syncthreads();

    // ph2: tid<128 -> Wv ; tid>=128 -> gh
    if (tid < 128) {
        float a4[NSL];
        gemvT<NSL,128,32>(WvT4, Y, 128, tid, a4);
        #pragma unroll
        for (int sl = 0; sl < NSL; sl++) UPD[sl*128 + tid] = a4[sl];
    } else {
        int r = tid - 128;
        float a4[NSL];
        gemvT<NSL,384,32>(WhhT4, SP, 128, r, a4);
        float bh = b_hh[r];
        #pragma unroll
        for (int sl = 0; sl < NSL; sl++) GH[sl*384 + r] = a4[sl] + bh;
    }
    __syncthreads();

    // ph3: gi
    if (tid < 384) {
        float a4[NSL];
        gemvT<NSL,384,32>(WihT4, UPD, 128, tid, a4);
        float bi = b_ih[tid];
        #pragma unroll
        for (int sl = 0; sl < NSL; sl++) GI[sl*384 + tid] = a4[sl] + bi;
    }
    __syncthreads();

    // ph4: GRU -> SMD
    for (int i = tid; i < NSL*128; i += 512) {
        int sl = i >> 7, h = i & 127;
        float gr = GI[sl*384 + h]       + GH[sl*384 + h];
        float gz = GI[sl*384 + 128 + h] + GH[sl*384 + 128 + h];
        float rr = 1.f/(1.f + __expf(-gr));
        float zz = 1.f/(1.f + __expf(-gz));
        float nn = tanhf(GI[sl*384 + 256 + h] + rr*GH[sl*384 + 256 + h]);
        SMD[i] = (1.f - zz)*nn + zz*SP[i];
    }
    __syncthreads();

    // ph5: LayerNorm(ln_m) -> SNM (warps 0..NSL-1)
    if (wid < NSL) {
        float4 x = *(const float4*)&SMD[wid*128 + lane*4];
        float sm = x.x+x.y+x.z+x.w;
        float sq = dot4(x, x);
        #pragma unroll
        for (int o = 16; o; o >>= 1) {
            sm += __shfl_xor_sync(0xffffffffu, sm, o);
            sq += __shfl_xor_sync(0xffffffffu, sq, o);
        }
        float m   = sm * (1.f/HH);
        float inv = rsqrtf(sq*(1.f/HH) - m*m + LN_EPS);
        int d = lane*4;
        SNM[wid*128+d+0] = (x.x-m)*inv*ln_m_g[d+0] + ln_m_b[d+0];
        SNM[wid*128+d+1] = (x.y-m)*inv*ln_m_g[d+1] + ln_m_b[d+1];
        SNM[wid*128+d+2] = (x.z-m)*inv*ln_m_g[d+2] + ln_m_b[d+2];
        SNM[wid*128+d+3] = (x.w-m)*inv*ln_m_g[d+3] + ln_m_b[d+3];
    }
    __syncthreads();

    // ph6: MLP1
    if (tid < 256) {
        float a4[NSL];
        gemvT<NSL,256,32>(w1T4, SNM, 128, tid, a4);
        float bb = b1[tid];
        #pragma unroll
        for (int sl = 0; sl < NSL; sl++)
            HID[sl*256 + tid] = fmaxf(a4[sl] + bb, 0.f);
    }
    __syncthreads();

    // ph7: MLP2 + residual -> final slots
    if (tid < 128) {
        float a4[NSL];
        gemvT<NSL,128,64>(w2T4, HID, 256, tid, a4);
        float bb = b2[tid];
        #pragma unroll
        for (int sl = 0; sl < NSL; sl++) {
            float v = SMD[sl*128 + tid] + a4[sl] + bb;
            SMD[sl*128 + tid] = v;
            if ((s0 + sl) < SS) {
                g_slots[b*SS*HH + (s0+sl)*128 + tid] = v;
                out    [b*SS*HH + (s0+sl)*128 + tid] = v;
            }
        }
    }
    __syncthreads();

    // ph8: prep for next iteration (local slots only)
    if (wid < NSL) {
        float4 x = *(const float4*)&SMD[wid*128 + lane*4];
        float sm = x.x+x.y+x.z+x.w;
        float sq = dot4(x, x);
        #pragma unroll
        for (int o = 16; o; o >>= 1) {
            sm += __shfl_xor_sync(0xffffffffu, sm, o);
            sq += __shfl_xor_sync(0xffffffffu, sq, o);
        }
        float m   = sm * (1.f/HH);
        float inv = rsqrtf(sq*(1.f/HH) - m*m + LN_EPS);
        int d = lane*4;
        SN2[wid*128+d+0] = (x.x-m)*inv*ln_s_g[d+0] + ln_s_b[d+0];
        SN2[wid*128+d+1] = (x.y-m)*inv*ln_s_g[d+1] + ln_s_b[d+1];
        SN2[wid*128+d+2] = (x.z-m)*inv*ln_s_g[d+2] + ln_s_b[d+2];
        SN2[wid*128+d+3] = (x.w-m)*inv*ln_s_g[d+3] + ln_s_b[d+3];
    }
    __syncthreads();

    if (tid < 128) {
        float a4[NSL];
        gemvT<NSL,128,32>(WqT4, SN2, 128, tid, a4);
        #pragma unroll
        for (int sl = 0; sl < NSL; sl++) Q2[sl*128 + tid] = a4[sl];
    }
    __syncthreads();

    float acc[NSL];
    if (tid < 128) {
        int d = tid;
        gemvT<NSL,128,32>(WkT4, Q2, 128, d, acc);
        float gg  = ln_in_g[d];
        float bbv = ln_in_b[d];
        float pe[NSL], pc[NSL];
        #pragma unroll
        for (int sl = 0; sl < NSL; sl++) {
            pe[sl] = SCALE * gg  * acc[sl];
            pc[sl] = SCALE * bbv * acc[sl];
        }
        #pragma unroll
        for (int o = 16; o; o >>= 1) {
            #pragma unroll
            for (int sl = 0; sl < NSL; sl++) {
                pe[sl] += __shfl_xor_sync(0xffffffffu, pe[sl], o);
                pc[sl] += __shfl_xor_sync(0xffffffffu, pc[sl], o);
            }
        }
        if (lane == 0) {
            #pragma unroll
            for (int sl = 0; sl < NSL; sl++) {
                atomicAdd(&red[sl],   pe[sl]);
                atomicAdd(&red[8+sl], pc[sl]);
            }
        }
    }
    __syncthreads();

    if (tid < 128) {
        int d = tid;
        float gg = ln_in_g[d];
        #pragma unroll
        for (int sl = 0; sl < NSL; sl++)
            if ((s0 + sl) < SS)
                g_u[(b*SS + s0+sl)*DD + d] = SCALE*gg*acc[sl] - red[sl]*(1.f/DD);
    }
    if (tid < NSL && (s0 + tid) < SS) {
        g_c[b*SS + s0 + tid]     = red[8+tid];
        g_W[b*SS + s0 + tid]     = 0.f;
        g_sumWM[b*SS + s0 + tid] = 0.f;
    }
    for (int i = tid; i < NSL*128; i += 512) {
        int sl = i >> 7, d = i & 127;
        if ((s0 + sl) < SS) g_acc[b*SS*DD + (s0+sl)*128 + d] = 0.f;
    }
}

// ---------------- launch ----------------
extern "C" void kernel_launch(void* const* d_in, const int* in_sizes, int n_in,
                              void* d_out, int out_size)
{
    const float* inputs     = (const float*)d_in[0];
    const float* slots_init = (const float*)d_in[1];
    const float* ln_in_g    = (const float*)d_in[2];
    const float* ln_in_b    = (const float*)d_in[3];
    const float* ln_s_g     = (const float*)d_in[4];
    const float* ln_s_b     = (const float*)d_in[5];
    const float* ln_m_g     = (const float*)d_in[6];
    const float* ln_m_b     = (const float*)d_in[7];
    const float* Wq         = (const float*)d_in[8];
    const float* Wk         = (const float*)d_in[9];
    const float* Wv         = (const float*)d_in[10];
    const float* W_ih       = (const float*)d_in[11];
    const float* W_hh       = (const float*)d_in[12];
    const float* b_ih       = (const float*)d_in[13];
    const float* b_hh       = (const float*)d_in[14];
    const float* mlp_w1     = (const float*)d_in[15];
    const float* mlp_b1     = (const float*)d_in[16];
    const float* mlp_w2     = (const float*)d_in[17];
    const float* mlp_b2     = (const float*)d_in[18];
    const float* slots_mu   = (const float*)d_in[19];
    const float* slots_lsig = (const float*)d_in[20];

    const int pass_smem = (TROWS*132 + 896 + TROWS*8*2 + 16) * 4;
    cudaFuncSetAttribute(k_pass, cudaFuncAttributeMaxDynamicSharedMemorySize,
                         pass_smem);

    k_tr<<<dim3(48, 7), 256>>>(Wv, W_ih, W_hh, mlp_w1, mlp_w2, Wq, Wk);
    k_init0<<<BB, 128>>>(slots_init, slots_mu, slots_lsig,
                         ln_s_g, ln_s_b, ln_in_g, ln_in_b);

    for (int it = 0; it < 3; it++) {
        k_pass<<<dim3(NN/TROWS, BB), 256, pass_smem>>>(inputs);
        k_upd<<<dim3(BB, 2), 512>>>(ln_in_g, ln_in_b, ln_m_g, ln_m_b,
                                    ln_s_g, ln_s_b,
                                    b_ih, b_hh, mlp_b1, mlp_b2,
                                    (float*)d_out);
    }
}